// round 9
// baseline (speedup 1.0000x reference)
#include <cuda_runtime.h>
#include <cstdint>

#define B_    2
#define NH_   8
#define N_    4096
#define D_    64
#define K2_   49
#define V_F4  784          // D*K2/4
#define THREADS 128
#define ROWS  8            // rows per CTA in av_stream
#define GR    64           // rows per CTA in gemv
#define TOK_PITCH 52       // 49 padded; 52*4=208B (16B multiple)

// 12.8 MB scratch for precomputed attention logits  [B,NH,N,K2]
__device__ float g_attn[(size_t)B_ * NH_ * N_ * K2_];

// ---------------------------------------------------------------------------
// helpers
// ---------------------------------------------------------------------------
__device__ __forceinline__ uint32_t smem_u32(const void* p) {
    return (uint32_t)__cvta_generic_to_shared(p);
}
__device__ __forceinline__ void cp16(uint32_t dst, const void* src) {
    asm volatile("cp.async.cg.shared.global [%0], [%1], 16;\n" :: "r"(dst), "l"(src));
}
__device__ __forceinline__ void cp4(uint32_t dst, const void* src) {
    asm volatile("cp.async.ca.shared.global [%0], [%1], 4;\n" :: "r"(dst), "l"(src));
}
__device__ __forceinline__ void cp_commit() {
    asm volatile("cp.async.commit_group;\n" ::: "memory");
}
template <int NPend>
__device__ __forceinline__ void cp_wait() {
    asm volatile("cp.async.wait_group %0;\n" :: "n"(NPend) : "memory");
}

// ---------------------------------------------------------------------------
// Kernel 1 (gemv): attn[row][k] = q[row] . tok[h][:,k] + bias + attn_local
// 64 rows/CTA, 2 threads per row: half0 -> k[0..27], half1 -> k[28..48]
// ---------------------------------------------------------------------------
template <int K0, int NF4, bool TAIL>
__device__ __forceinline__ void gemv_half(const float4* __restrict__ qr,
                                          const float* __restrict__ s_tok,
                                          float* __restrict__ s_row_out)
{
    float4 acc[NF4];
    float  acct = 0.f;
#pragma unroll
    for (int i = 0; i < NF4; i++) acc[i] = make_float4(0.f, 0.f, 0.f, 0.f);

#pragma unroll
    for (int c = 0; c < D_ / 4; c++) {
        const float4 qv = __ldg(qr + c);
        const float qs[4] = {qv.x, qv.y, qv.z, qv.w};
#pragma unroll
        for (int j = 0; j < 4; j++) {
            const int d = 4 * c + j;
            const float qd = qs[j];
            const float4* trow =
                reinterpret_cast<const float4*>(s_tok + d * TOK_PITCH + K0);
#pragma unroll
            for (int i = 0; i < NF4; i++) {          // broadcast LDS.128
                const float4 tv = trow[i];
                acc[i].x = fmaf(qd, tv.x, acc[i].x);
                acc[i].y = fmaf(qd, tv.y, acc[i].y);
                acc[i].z = fmaf(qd, tv.z, acc[i].z);
                acc[i].w = fmaf(qd, tv.w, acc[i].w);
            }
            if (TAIL)
                acct = fmaf(qd, s_tok[d * TOK_PITCH + 48], acct);
        }
    }
#pragma unroll
    for (int i = 0; i < NF4; i++) {
        s_row_out[K0 + 4 * i + 0] = acc[i].x;
        s_row_out[K0 + 4 * i + 1] = acc[i].y;
        s_row_out[K0 + 4 * i + 2] = acc[i].z;
        s_row_out[K0 + 4 * i + 3] = acc[i].w;
    }
    if (TAIL) s_row_out[48] = acct;
}

__global__ __launch_bounds__(THREADS, 8)
void attn_gemv_kernel(const float* __restrict__ q_norm,      // [B,NH,N,D]
                      const float* __restrict__ attn_local,  // [B,NH,N,K2]
                      const float* __restrict__ tokens,      // [NH,D,K2]
                      const float* __restrict__ bias)        // [NH,N,K2]
{
    __shared__ float s_tok[D_ * TOK_PITCH];   // 13312 B
    __shared__ float s_out[GR * K2_];         // 12544 B

    const int t    = threadIdx.x;
    const int row0 = blockIdx.x * GR;
    const int h    = (row0 >> 12) & (NH_ - 1);

    // tokens[h] -> smem, padded pitch
    {
        const float* tk = tokens + h * (D_ * K2_);
        for (int i = t; i < D_ * K2_; i += THREADS)
            s_tok[(i / K2_) * TOK_PITCH + (i % K2_)] = __ldg(tk + i);
    }
    __syncthreads();

    const int rl   = t >> 1;                       // row-in-CTA 0..63
    const int half = t & 1;
    const int row  = row0 + rl;
    const float4* qr = reinterpret_cast<const float4*>(q_norm + (size_t)row * D_);
    float* so = s_out + rl * K2_;

    if (half == 0)  gemv_half<0, 7, false>(qr, s_tok, so);   // k 0..27
    else            gemv_half<28, 5, true>(qr, s_tok, so);   // k 28..48
    __syncthreads();

    // coalesced epilogue: += attn_local + bias, write to g_attn
    const int n0 = row0 & (N_ - 1);
    const float* al0 = attn_local + (size_t)row0 * K2_;
    const float* b0  = bias + ((size_t)h * N_ + n0) * K2_;
    float* dst = g_attn + (size_t)row0 * K2_;
    for (int i = t; i < GR * K2_; i += THREADS)
        dst[i] = s_out[i] + __ldg(al0 + i) + __ldg(b0 + i);
}

// ---------------------------------------------------------------------------
// Kernel 2 (unchanged from R7: 130us @ 82.7% DRAM)
// ---------------------------------------------------------------------------
struct __align__(16) Stage {
    float4 v[V_F4];        // 12544 B
    float  a[K2_];         // 196 B
    float  pad[3];         // sizeof = 12752 (16B multiple)
};

__global__ __launch_bounds__(THREADS)
void av_stream_kernel(const float* __restrict__ v_local,     // [B,NH,N,D,K2]
                      float* __restrict__ out)               // [B,NH,N,D]
{
    __shared__ Stage st[2];

    const int t    = threadIdx.x;
    const int row0 = blockIdx.x * ROWS;

    auto prefetch = [&](int s, int row) {
        const float4* vrow = reinterpret_cast<const float4*>(v_local) + (size_t)row * V_F4;
        uint32_t vdst = smem_u32(st[s].v);
#pragma unroll
        for (int i = 0; i < 6; i++)
            cp16(vdst + (uint32_t)(t + THREADS * i) * 16u, vrow + t + THREADS * i);
        if (t < V_F4 - 6 * THREADS)                   // 16 leftover float4
            cp16(vdst + (uint32_t)(t + 6 * THREADS) * 16u, vrow + t + 6 * THREADS);

        if (t < K2_)
            cp4(smem_u32(st[s].a) + (uint32_t)t * 4u, g_attn + (size_t)row * K2_ + t);
        cp_commit();
    };

    prefetch(0, row0);

    for (int r = 0; r < ROWS; r++) {
        if (r + 1 < ROWS) {
            prefetch((r + 1) & 1, row0 + r + 1);
            cp_wait<1>();
        } else {
            cp_wait<0>();
        }
        __syncthreads();                              // stage r&1 ready

        const Stage& S = st[r & 1];

        if (t < D_) {
            const float* vd = reinterpret_cast<const float*>(S.v) + t * K2_;
            float acc0 = 0.f, acc1 = 0.f;
#pragma unroll
            for (int k = 0; k < 48; k += 2) {
                acc0 = fmaf(S.a[k + 0], vd[k + 0], acc0);
                acc1 = fmaf(S.a[k + 1], vd[k + 1], acc1);
            }
            acc0 = fmaf(S.a[48], vd[48], acc0);
            out[(size_t)(row0 + r) * D_ + t] = acc0 + acc1;
        }

        __syncthreads();                              // readers done before overwrite
    }
}

// ---------------------------------------------------------------------------
extern "C" void kernel_launch(void* const* d_in, const int* in_sizes, int n_in,
                              void* d_out, int out_size)
{
    const float* q_norm     = (const float*)d_in[0];
    const float* attn_local = (const float*)d_in[1];
    const float* v_local    = (const float*)d_in[2];
    const float* tokens     = (const float*)d_in[3];
    const float* bias       = (const float*)d_in[4];
    float* out = (float*)d_out;

    attn_gemv_kernel<<<(B_ * NH_ * N_) / GR, THREADS>>>(q_norm, attn_local, tokens, bias);
    av_stream_kernel<<<(B_ * NH_ * N_) / ROWS, THREADS>>>(v_local, out);
}

// round 10
// speedup vs baseline: 1.0039x; 1.0039x over previous
#include <cuda_runtime.h>
#include <cstdint>

#define B_    2
#define NH_   8
#define N_    4096
#define D_    64
#define K2_   49
#define V_F4  784          // D*K2/4
#define THREADS 128
#define ROWS  8            // rows per CTA in av_stream
#define GR    64           // rows per CTA in gemv
#define TOK_PITCH 52       // 49 padded; 52*4=208B (16B multiple)

// 12.8 MB scratch for precomputed attention logits  [B,NH,N,K2]
__device__ float g_attn[(size_t)B_ * NH_ * N_ * K2_];

// ---------------------------------------------------------------------------
// helpers
// ---------------------------------------------------------------------------
__device__ __forceinline__ uint32_t smem_u32(const void* p) {
    return (uint32_t)__cvta_generic_to_shared(p);
}
__device__ __forceinline__ void cp16(uint32_t dst, const void* src) {
    asm volatile("cp.async.cg.shared.global [%0], [%1], 16;\n" :: "r"(dst), "l"(src));
}
__device__ __forceinline__ void cp4(uint32_t dst, const void* src) {
    asm volatile("cp.async.ca.shared.global [%0], [%1], 4;\n" :: "r"(dst), "l"(src));
}
__device__ __forceinline__ void cp_commit() {
    asm volatile("cp.async.commit_group;\n" ::: "memory");
}
template <int NPend>
__device__ __forceinline__ void cp_wait() {
    asm volatile("cp.async.wait_group %0;\n" :: "n"(NPend) : "memory");
}

// ---------------------------------------------------------------------------
// Kernel 1 (gemv): attn[row][k] = q[row] . tok[h][:,k] + bias + attn_local
// 64 rows/CTA, 2 threads per row: half0 -> k[0..27], half1 -> k[28..48]
// ---------------------------------------------------------------------------
template <int K0, int NF4, bool TAIL>
__device__ __forceinline__ void gemv_half(const float4* __restrict__ qr,
                                          const float* __restrict__ s_tok,
                                          float* __restrict__ s_row_out)
{
    float4 acc[NF4];
    float  acct = 0.f;
#pragma unroll
    for (int i = 0; i < NF4; i++) acc[i] = make_float4(0.f, 0.f, 0.f, 0.f);

#pragma unroll
    for (int c = 0; c < D_ / 4; c++) {
        const float4 qv = __ldg(qr + c);
        const float qs[4] = {qv.x, qv.y, qv.z, qv.w};
#pragma unroll
        for (int j = 0; j < 4; j++) {
            const int d = 4 * c + j;
            const float qd = qs[j];
            const float4* trow =
                reinterpret_cast<const float4*>(s_tok + d * TOK_PITCH + K0);
#pragma unroll
            for (int i = 0; i < NF4; i++) {          // broadcast LDS.128
                const float4 tv = trow[i];
                acc[i].x = fmaf(qd, tv.x, acc[i].x);
                acc[i].y = fmaf(qd, tv.y, acc[i].y);
                acc[i].z = fmaf(qd, tv.z, acc[i].z);
                acc[i].w = fmaf(qd, tv.w, acc[i].w);
            }
            if (TAIL)
                acct = fmaf(qd, s_tok[d * TOK_PITCH + 48], acct);
        }
    }
#pragma unroll
    for (int i = 0; i < NF4; i++) {
        s_row_out[K0 + 4 * i + 0] = acc[i].x;
        s_row_out[K0 + 4 * i + 1] = acc[i].y;
        s_row_out[K0 + 4 * i + 2] = acc[i].z;
        s_row_out[K0 + 4 * i + 3] = acc[i].w;
    }
    if (TAIL) s_row_out[48] = acct;
}

__global__ __launch_bounds__(THREADS)   // NO min-blocks clamp: let regs float (~56)
void attn_gemv_kernel(const float* __restrict__ q_norm,      // [B,NH,N,D]
                      const float* __restrict__ attn_local,  // [B,NH,N,K2]
                      const float* __restrict__ tokens,      // [NH,D,K2]
                      const float* __restrict__ bias)        // [NH,N,K2]
{
    __shared__ float s_tok[D_ * TOK_PITCH];   // 13312 B
    __shared__ float s_out[GR * K2_];         // 12544 B

    const int t    = threadIdx.x;
    const int row0 = blockIdx.x * GR;
    const int h    = (row0 >> 12) & (NH_ - 1);

    // tokens[h] -> smem, padded pitch
    {
        const float* tk = tokens + h * (D_ * K2_);
        for (int i = t; i < D_ * K2_; i += THREADS)
            s_tok[(i / K2_) * TOK_PITCH + (i % K2_)] = __ldg(tk + i);
    }
    __syncthreads();

    const int rl   = t >> 1;                       // row-in-CTA 0..63
    const int half = t & 1;
    const int row  = row0 + rl;
    const float4* qr = reinterpret_cast<const float4*>(q_norm + (size_t)row * D_);
    float* so = s_out + rl * K2_;

    if (half == 0)  gemv_half<0, 7, false>(qr, s_tok, so);   // k 0..27
    else            gemv_half<28, 5, true>(qr, s_tok, so);   // k 28..48
    __syncthreads();

    // coalesced epilogue: += attn_local + bias, write to g_attn
    const int n0 = row0 & (N_ - 1);
    const float* al0 = attn_local + (size_t)row0 * K2_;
    const float* b0  = bias + ((size_t)h * N_ + n0) * K2_;
    float* dst = g_attn + (size_t)row0 * K2_;
    for (int i = t; i < GR * K2_; i += THREADS)
        dst[i] = s_out[i] + __ldg(al0 + i) + __ldg(b0 + i);
}

// ---------------------------------------------------------------------------
// Kernel 2 (unchanged: 129.5us @ 83% DRAM, verified twice)
// ---------------------------------------------------------------------------
struct __align__(16) Stage {
    float4 v[V_F4];        // 12544 B
    float  a[K2_];         // 196 B
    float  pad[3];         // sizeof = 12752 (16B multiple)
};

__global__ __launch_bounds__(THREADS)
void av_stream_kernel(const float* __restrict__ v_local,     // [B,NH,N,D,K2]
                      float* __restrict__ out)               // [B,NH,N,D]
{
    __shared__ Stage st[2];

    const int t    = threadIdx.x;
    const int row0 = blockIdx.x * ROWS;

    auto prefetch = [&](int s, int row) {
        const float4* vrow = reinterpret_cast<const float4*>(v_local) + (size_t)row * V_F4;
        uint32_t vdst = smem_u32(st[s].v);
#pragma unroll
        for (int i = 0; i < 6; i++)
            cp16(vdst + (uint32_t)(t + THREADS * i) * 16u, vrow + t + THREADS * i);
        if (t < V_F4 - 6 * THREADS)                   // 16 leftover float4
            cp16(vdst + (uint32_t)(t + 6 * THREADS) * 16u, vrow + t + 6 * THREADS);

        if (t < K2_)
            cp4(smem_u32(st[s].a) + (uint32_t)t * 4u, g_attn + (size_t)row * K2_ + t);
        cp_commit();
    };

    prefetch(0, row0);

    for (int r = 0; r < ROWS; r++) {
        if (r + 1 < ROWS) {
            prefetch((r + 1) & 1, row0 + r + 1);
            cp_wait<1>();
        } else {
            cp_wait<0>();
        }
        __syncthreads();                              // stage r&1 ready

        const Stage& S = st[r & 1];

        if (t < D_) {
            const float* vd = reinterpret_cast<const float*>(S.v) + t * K2_;
            float acc0 = 0.f, acc1 = 0.f;
#pragma unroll
            for (int k = 0; k < 48; k += 2) {
                acc0 = fmaf(S.a[k + 0], vd[k + 0], acc0);
                acc1 = fmaf(S.a[k + 1], vd[k + 1], acc1);
            }
            acc0 = fmaf(S.a[48], vd[48], acc0);
            out[(size_t)(row0 + r) * D_ + t] = acc0 + acc1;
        }

        __syncthreads();                              // readers done before overwrite
    }
}

// ---------------------------------------------------------------------------
extern "C" void kernel_launch(void* const* d_in, const int* in_sizes, int n_in,
                              void* d_out, int out_size)
{
    const float* q_norm     = (const float*)d_in[0];
    const float* attn_local = (const float*)d_in[1];
    const float* v_local    = (const float*)d_in[2];
    const float* tokens     = (const float*)d_in[3];
    const float* bias       = (const float*)d_in[4];
    float* out = (float*)d_out;

    attn_gemv_kernel<<<(B_ * NH_ * N_) / GR, THREADS>>>(q_norm, attn_local, tokens, bias);
    av_stream_kernel<<<(B_ * NH_ * N_) / ROWS, THREADS>>>(v_local, out);
}

// round 11
// speedup vs baseline: 1.0375x; 1.0335x over previous
#include <cuda_runtime.h>
#include <cstdint>

#define B_    2
#define NH_   8
#define N_    4096
#define D_    64
#define K2_   49
#define V_F4  784          // D*K2/4
#define THREADS 128
#define ROWS  8            // rows per CTA (8 | 4096 so h constant per CTA)

__device__ __forceinline__ uint32_t smem_u32(const void* p) {
    return (uint32_t)__cvta_generic_to_shared(p);
}
__device__ __forceinline__ void cp16(uint32_t dst, const void* src) {
    // .cg: v_local is pure streaming, keep it out of L1
    asm volatile("cp.async.cg.shared.global [%0], [%1], 16;\n" :: "r"(dst), "l"(src));
}
__device__ __forceinline__ void cp_commit() {
    asm volatile("cp.async.commit_group;\n" ::: "memory");
}
template <int NPend>
__device__ __forceinline__ void cp_wait() {
    asm volatile("cp.async.wait_group %0;\n" :: "n"(NPend) : "memory");
}

struct __align__(16) Stage {
    float4 v[V_F4];        // 12544 B
};

__global__ __launch_bounds__(THREADS)
void sw_attention_av_fused3(const float* __restrict__ q_norm,      // [B,NH,N,D]
                            const float* __restrict__ attn_local,  // [B,NH,N,K2]
                            const float* __restrict__ v_local,     // [B,NH,N,D,K2]
                            const float* __restrict__ tokens,      // [NH,D,K2]
                            const float* __restrict__ bias,        // [NH,N,K2]
                            float* __restrict__ out)               // [B,NH,N,D]
{
    __shared__ Stage st[2];                 // 25088 B
    __shared__ float s_attn[ROWS * K2_];    // 1568 B

    const int t    = threadIdx.x;
    const int wid  = t >> 5;
    const int lane = t & 31;
    const int row0 = blockIdx.x * ROWS;
    const int h    = (row0 >> 12) & (NH_ - 1);
    const int n0   = row0 & (N_ - 1);

    auto prefetch_v = [&](int s, int row) {
        const float4* vrow = reinterpret_cast<const float4*>(v_local) + (size_t)row * V_F4;
        uint32_t vdst = smem_u32(st[s].v);
#pragma unroll
        for (int i = 0; i < 6; i++)
            cp16(vdst + (uint32_t)(t + THREADS * i) * 16u, vrow + t + THREADS * i);
        if (t < V_F4 - 6 * THREADS)                 // 16 leftover float4
            cp16(vdst + (uint32_t)(t + 6 * THREADS) * 16u, vrow + t + 6 * THREADS);
        cp_commit();
    };

    // ---- prologue: get rows 0 and 1 streaming immediately
    prefetch_v(0, row0);
    prefetch_v(1, row0 + 1);

    // ---- gemv burst (overlaps the two stage fills):
    // warp w owns rows 2w, 2w+1; k mapped to lanes -> tokens loads are
    // one coalesced 128B warp-load per d; q is a 1-sector broadcast.
    {
        const float* tok_h = tokens + h * (D_ * K2_);
        const float* al0   = attn_local + (size_t)row0 * K2_;
        const float* b0    = bias + ((size_t)h * N_ + n0) * K2_;
#pragma unroll
        for (int rr = 0; rr < 2; rr++) {
            const int r = 2 * wid + rr;
            const float* qp = q_norm + (size_t)(row0 + r) * D_;
#pragma unroll
            for (int c = 0; c < 2; c++) {
                const int k = c * 32 + lane;
                if (k < K2_) {
                    const float* tp = tok_h + k;
                    float a0 = 0.f, a1 = 0.f, a2 = 0.f, a3 = 0.f;
#pragma unroll
                    for (int d = 0; d < D_; d += 4) {
                        a0 = fmaf(__ldg(qp + d + 0), __ldg(tp + (d + 0) * K2_), a0);
                        a1 = fmaf(__ldg(qp + d + 1), __ldg(tp + (d + 1) * K2_), a1);
                        a2 = fmaf(__ldg(qp + d + 2), __ldg(tp + (d + 2) * K2_), a2);
                        a3 = fmaf(__ldg(qp + d + 3), __ldg(tp + (d + 3) * K2_), a3);
                    }
                    s_attn[r * K2_ + k] = (a0 + a1) + (a2 + a3)
                                        + __ldg(al0 + r * K2_ + k)
                                        + __ldg(b0  + r * K2_ + k);
                }
            }
        }
    }
    __syncthreads();                                // s_attn visible to all

    // ---- steady-state streaming loop (identical to the 83%-DRAM kernel)
    for (int r = 0; r < ROWS; r++) {
        if (r + 1 < ROWS) cp_wait<1>();             // row r landed (FIFO groups)
        else              cp_wait<0>();
        __syncthreads();                            // stage r&1 visible

        const Stage& S = st[r & 1];

        if (t < D_) {
            const float* vd = reinterpret_cast<const float*>(S.v) + t * K2_;
            const float* ak = s_attn + r * K2_;
            float acc0 = 0.f, acc1 = 0.f;
#pragma unroll
            for (int k = 0; k < 48; k += 2) {
                acc0 = fmaf(ak[k + 0], vd[k + 0], acc0);
                acc1 = fmaf(ak[k + 1], vd[k + 1], acc1);
            }
            acc0 = fmaf(ak[48], vd[48], acc0);
            out[(size_t)(row0 + r) * D_ + t] = acc0 + acc1;
        }

        __syncthreads();                            // readers done with slot r&1

        if (r + 2 < ROWS)
            prefetch_v(r & 1, row0 + r + 2);        // refill the freed slot
    }
}

extern "C" void kernel_launch(void* const* d_in, const int* in_sizes, int n_in,
                              void* d_out, int out_size)
{
    const float* q_norm     = (const float*)d_in[0];
    const float* attn_local = (const float*)d_in[1];
    const float* v_local    = (const float*)d_in[2];
    const float* tokens     = (const float*)d_in[3];
    const float* bias       = (const float*)d_in[4];
    float* out = (float*)d_out;

    const int blocks = (B_ * NH_ * N_) / ROWS;      // 8192
    sw_attention_av_fused3<<<blocks, THREADS>>>(q_norm, attn_local, v_local,
                                                tokens, bias, out);
}

// round 12
// speedup vs baseline: 1.1653x; 1.1232x over previous
#include <cuda_runtime.h>
#include <cstdint>

#define B_    2
#define NH_   8
#define N_    4096
#define D_    64
#define K2_   49
#define V_F4  784          // D*K2/4
#define THREADS 128
#define ROWS  8            // rows per CTA (8 | 4096 so h constant per CTA)

__device__ __forceinline__ uint32_t smem_u32(const void* p) {
    return (uint32_t)__cvta_generic_to_shared(p);
}
__device__ __forceinline__ void cp16(uint32_t dst, const void* src) {
    // .cg: v_local is pure streaming, keep it out of L1
    asm volatile("cp.async.cg.shared.global [%0], [%1], 16;\n" :: "r"(dst), "l"(src));
}
__device__ __forceinline__ void cp_commit() {
    asm volatile("cp.async.commit_group;\n" ::: "memory");
}
template <int NPend>
__device__ __forceinline__ void cp_wait() {
    asm volatile("cp.async.wait_group %0;\n" :: "n"(NPend) : "memory");
}

struct __align__(16) Stage {
    float4 v[V_F4];        // 12544 B (v only; q/al/bias moved out)
};

__global__ __launch_bounds__(THREADS)
void sw_attention_av_overlap(const float* __restrict__ q_norm,      // [B,NH,N,D]
                             const float* __restrict__ attn_local,  // [B,NH,N,K2]
                             const float* __restrict__ v_local,     // [B,NH,N,D,K2]
                             const float* __restrict__ tokens,      // [NH,D,K2]
                             const float* __restrict__ bias,        // [NH,N,K2]
                             float* __restrict__ out)               // [B,NH,N,D]
{
    __shared__ Stage st[2];                  // 25088 B
    __shared__ float s_q[ROWS * D_];         // 2048 B  (all 8 rows' q)
    __shared__ float s_attn[2][K2_];         // 392 B   (double-buffered)

    const int t    = threadIdx.x;
    const int row0 = blockIdx.x * ROWS;
    const int h    = (row0 >> 12) & (NH_ - 1);
    const int n0   = row0 & (N_ - 1);
    const float* tok_h = tokens + h * (D_ * K2_);

    auto prefetch_v = [&](int s, int row) {
        const float4* vrow = reinterpret_cast<const float4*>(v_local) + (size_t)row * V_F4;
        uint32_t vdst = smem_u32(st[s].v);
#pragma unroll
        for (int i = 0; i < 6; i++)
            cp16(vdst + (uint32_t)(t + THREADS * i) * 16u, vrow + t + THREADS * i);
        if (t < V_F4 - 6 * THREADS)                 // 16 leftover float4
            cp16(vdst + (uint32_t)(t + 6 * THREADS) * 16u, vrow + t + 6 * THREADS);
        cp_commit();
    };

    // phase 1 for CTA-local row rr (warps 2-3 only): attn[rr][k]
    auto phase1 = [&](int rr) {
        int k = (t < 96) ? (t - 64) : (t - 96 + 32);   // warp2: 0..31, warp3: 32..63
        if (k < K2_) {
            const float* qrow = s_q + rr * D_;          // LDS broadcast
            const float* tp   = tok_h + k;              // coalesced LDG (L1/L2-hot)
            float a0 = 0.f, a1 = 0.f, a2 = 0.f, a3 = 0.f;
#pragma unroll
            for (int d = 0; d < D_; d += 4) {
                a0 = fmaf(qrow[d + 0], __ldg(tp + (d + 0) * K2_), a0);
                a1 = fmaf(qrow[d + 1], __ldg(tp + (d + 1) * K2_), a1);
                a2 = fmaf(qrow[d + 2], __ldg(tp + (d + 2) * K2_), a2);
                a3 = fmaf(qrow[d + 3], __ldg(tp + (d + 3) * K2_), a3);
            }
            a0 = (a0 + a1) + (a2 + a3)
               + __ldg(attn_local + (size_t)(row0 + rr) * K2_ + k)
               + __ldg(bias + ((size_t)h * N_ + n0 + rr) * K2_ + k);
            s_attn[rr & 1][k] = a0;
        }
    };

    // ---- prologue: group0 = q (all 8 rows, contiguous 512 floats), group1 = v0
    cp16(smem_u32(s_q) + (uint32_t)t * 16u,
         reinterpret_cast<const float4*>(q_norm + (size_t)row0 * D_) + t);
    cp_commit();
    prefetch_v(0, row0);
    cp_wait<1>();                       // q landed (v0 still streaming)
    __syncthreads();                    // all threads' q slices visible

    if (t >= 64) phase1(0);             // warps 2-3: attn row 0 while v0 streams

    // ---- steady loop: phase2(r) || phase1(r+1)
    for (int r = 0; r < ROWS; r++) {
        if (r + 1 < ROWS) {
            prefetch_v((r + 1) & 1, row0 + r + 1);   // slot freed at end of r-1
            cp_wait<1>();                            // stage r complete
        } else {
            cp_wait<0>();
        }
        __syncthreads();                // stage r + s_attn[r&1] visible to all

        if (t < D_) {
            // -------- phase 2: out[row r][d=t] --------
            const float* vd = reinterpret_cast<const float*>(st[r & 1].v) + t * K2_;
            const float* ak = s_attn[r & 1];
            float acc0 = 0.f, acc1 = 0.f;
#pragma unroll
            for (int k = 0; k < 48; k += 2) {
                acc0 = fmaf(ak[k + 0], vd[k + 0], acc0);
                acc1 = fmaf(ak[k + 1], vd[k + 1], acc1);
            }
            acc0 = fmaf(ak[48], vd[48], acc0);
            out[(size_t)(row0 + r) * D_ + t] = acc0 + acc1;
        } else if (r + 1 < ROWS) {
            // -------- phase 1 for row r+1 (buffer (r+1)&1, read next iter) --------
            phase1(r + 1);
        }

        __syncthreads();                // phase2 readers done -> slot r&1 reusable
    }
}

extern "C" void kernel_launch(void* const* d_in, const int* in_sizes, int n_in,
                              void* d_out, int out_size)
{
    const float* q_norm     = (const float*)d_in[0];
    const float* attn_local = (const float*)d_in[1];
    const float* v_local    = (const float*)d_in[2];
    const float* tokens     = (const float*)d_in[3];
    const float* bias       = (const float*)d_in[4];
    float* out = (float*)d_out;

    const int blocks = (B_ * NH_ * N_) / ROWS;      // 8192
    sw_attention_av_overlap<<<blocks, THREADS>>>(q_norm, attn_local, v_local,
                                                 tokens, bias, out);
}